// round 2
// baseline (speedup 1.0000x reference)
#include <cuda_runtime.h>

// Bidirectional tanh-Elman RNN, B=32, S=2048, D=H=256, fp32.
// Persistent kernel: 128 CTAs (64/direction), device-wide spin barrier per step.
// Each CTA owns a 16-column slice of Wh & Wx (smem-resident) and 8 batch rows.
// h state ping-pongs through L2 (ldcg/stcg; L1 is not coherent across SMs).

#define B_SZ 32
#define S_SZ 2048
#define D_SZ 256
#define H_SZ 256

#define NBLK_DIR 64      // blocks per direction
#define JT 16            // columns per block
#define BT 8             // batch rows per block

// persistent device state (allowed: __device__ globals, no allocation)
__device__ float g_h[2][2][B_SZ * H_SZ];   // [dir][parity][b*H + j]
__device__ unsigned g_bar[2];              // per-direction barrier counters

__global__ void reset_kernel() {
    int gid = blockIdx.x * blockDim.x + threadIdx.x;
    if (gid < 2 * B_SZ * H_SZ) {
        int dir = gid / (B_SZ * H_SZ);
        g_h[dir][0][gid % (B_SZ * H_SZ)] = 0.0f;
    }
    if (gid < 2) g_bar[gid] = 0u;
}

// dynamic smem layout (floats):
//   sWh  [0,     4096)   Wh[:, j0:j0+16]   row i * 16 + jt
//   sWx  [4096,  8192)   Wx[:, j0:j0+16]
//   sRed [8192,  9216)   float4[256] k-partials
//   sH   [9216, 11520)   h transposed, pitch 9: sH[i*9 + b]
//   sX   [11520,13824)   x_t transposed, pitch 9
//   sB   [13824,13840)   bias slice
#define SMEM_FLOATS 13840
#define SMEM_BYTES  (SMEM_FLOATS * 4)

__global__ __launch_bounds__(256, 1) void rnn_kernel(
    const float* __restrict__ x,
    const float* __restrict__ Wx_f, const float* __restrict__ Wh_f, const float* __restrict__ b_f,
    const float* __restrict__ Wx_b, const float* __restrict__ Wh_b, const float* __restrict__ b_b,
    float* __restrict__ out)
{
    extern __shared__ float sm[];
    float* sWh  = sm;
    float* sWx  = sm + 4096;
    float* sRed = sm + 8192;
    float* sH   = sm + 9216;
    float* sX   = sm + 11520;
    float* sB   = sm + 13824;

    const int t   = threadIdx.x;
    const int dir = blockIdx.x >> 6;        // 0 = fwd, 1 = bwd
    const int blk = blockIdx.x & 63;
    const int j0  = (blk & 15) << 4;        // 16 j-slices of 16 cols
    const int b0  = (blk >> 4) << 3;        // 4 b-slices of 8 rows

    const float* Wx   = dir ? Wx_b : Wx_f;
    const float* Wh   = dir ? Wh_b : Wh_f;
    const float* bias = dir ? b_b  : b_f;

    // preload weight slices into smem (once)
    for (int idx = t; idx < 4096; idx += 256) {
        int i = idx >> 4, jt = idx & 15;
        sWh[idx] = Wh[i * H_SZ + j0 + jt];
        sWx[idx] = Wx[i * H_SZ + j0 + jt];
    }
    if (t < 16) sB[t] = bias[j0 + t];
    __syncthreads();

    // compute-thread coordinates: 4 j-quad x 8 batch x 8 k-chunks
    const int jq  = t & 3;           // j-quad (4 cols via float4)
    const int bb  = (t >> 2) & 7;    // batch row within slice
    const int kk  = t >> 5;          // k-chunk (warp id)
    const int ib  = kk << 5;         // 32 i's per chunk

    for (int s = 0; s < S_SZ; ++s) {
        const int sx = dir ? (S_SZ - 1 - s) : s;

        // stage h (L2, coherent via ldcg) and x_t into smem, transposed [i][b] pitch 9
        const float* hsrc = g_h[dir][s & 1];
        #pragma unroll
        for (int r = 0; r < 2; ++r) {
            int q  = t + (r << 8);        // 0..511 quads
            int b  = q >> 6;              // 0..7
            int iq = (q & 63) << 2;       // 0..252
            float4 hv = __ldcg((const float4*)(hsrc + (b0 + b) * H_SZ + iq));
            sH[(iq + 0) * 9 + b] = hv.x;
            sH[(iq + 1) * 9 + b] = hv.y;
            sH[(iq + 2) * 9 + b] = hv.z;
            sH[(iq + 3) * 9 + b] = hv.w;
            float4 xv = *(const float4*)(x + ((size_t)(b0 + b) * S_SZ + sx) * D_SZ + iq);
            sX[(iq + 0) * 9 + b] = xv.x;
            sX[(iq + 1) * 9 + b] = xv.y;
            sX[(iq + 2) * 9 + b] = xv.z;
            sX[(iq + 3) * 9 + b] = xv.w;
        }
        __syncthreads();

        // partial dot products: acc[j] = sum_{i in chunk} h[b][i]*Wh[i][j] + x[b][i]*Wx[i][j]
        float4 acc = make_float4(0.f, 0.f, 0.f, 0.f);
        #pragma unroll
        for (int ii = 0; ii < 32; ++ii) {
            int i = ib + ii;
            float  hv = sH[i * 9 + bb];
            float4 w  = *(const float4*)(sWh + (i << 4) + (jq << 2));
            acc.x = fmaf(hv, w.x, acc.x);
            acc.y = fmaf(hv, w.y, acc.y);
            acc.z = fmaf(hv, w.z, acc.z);
            acc.w = fmaf(hv, w.w, acc.w);
        }
        #pragma unroll
        for (int ii = 0; ii < 32; ++ii) {
            int i = ib + ii;
            float  xv = sX[i * 9 + bb];
            float4 w  = *(const float4*)(sWx + (i << 4) + (jq << 2));
            acc.x = fmaf(xv, w.x, acc.x);
            acc.y = fmaf(xv, w.y, acc.y);
            acc.z = fmaf(xv, w.z, acc.z);
            acc.w = fmaf(xv, w.w, acc.w);
        }
        ((float4*)sRed)[t] = acc;
        __syncthreads();

        // reduce 8 k-partials, add bias, tanh, write h_next + output
        if (t < 128) {
            int jt = t & 15;
            int b  = t >> 4;
            float sum = sB[jt];
            #pragma unroll
            for (int k = 0; k < 8; ++k)
                sum += sRed[jt + (b << 4) + (k << 7)];
            float hnew = tanhf(sum);
            __stcg(&g_h[dir][(s + 1) & 1][(b0 + b) * H_SZ + j0 + jt], hnew);
            out[((size_t)(b0 + b) * S_SZ + sx) * (2 * H_SZ) + dir * H_SZ + j0 + jt] = hnew;
        }

        // per-direction grid barrier (skip after last step)
        if (s + 1 < S_SZ) {
            __threadfence();
            __syncthreads();
            if (t == 0) {
                unsigned target = (unsigned)NBLK_DIR * (unsigned)(s + 1);
                atomicAdd(&g_bar[dir], 1u);
                while (atomicAdd(&g_bar[dir], 0u) < target)
                    __nanosleep(32);
                __threadfence();
            }
            __syncthreads();
        }
    }
}

extern "C" void kernel_launch(void* const* d_in, const int* in_sizes, int n_in,
                              void* d_out, int out_size)
{
    const float* x    = (const float*)d_in[0];
    const float* Wx_f = (const float*)d_in[1];
    const float* Wh_f = (const float*)d_in[2];
    const float* b_f  = (const float*)d_in[3];
    const float* Wx_b = (const float*)d_in[4];
    const float* Wh_b = (const float*)d_in[5];
    const float* b_b  = (const float*)d_in[6];
    float* out = (float*)d_out;

    cudaFuncSetAttribute(rnn_kernel, cudaFuncAttributeMaxDynamicSharedMemorySize, SMEM_BYTES);

    reset_kernel<<<16, 1024>>>();
    rnn_kernel<<<2 * NBLK_DIR, 256, SMEM_BYTES>>>(x, Wx_f, Wh_f, b_f, Wx_b, Wh_b, b_b, out);
}

// round 3
// speedup vs baseline: 1.0207x; 1.0207x over previous
#include <cuda_runtime.h>

// Bidirectional tanh-Elman RNN, B=32, S=2048, D=H=256, fp32.
// Persistent kernel: 128 CTAs (64/direction), device-wide spin barrier per step.
// Each CTA owns a 16-column slice of Wh & Wx (smem-resident) and 8 batch rows.
// h state ping-pongs through L2 (ldcg/stcg; L1 is not coherent across SMs).

#define B_SZ 32
#define S_SZ 2048
#define D_SZ 256
#define H_SZ 256

#define NBLK_DIR 64      // blocks per direction
#define JT 16            // columns per block
#define BT 8             // batch rows per block

// persistent device state (allowed: __device__ globals, no allocation)
__device__ float g_h[2][2][B_SZ * H_SZ];   // [dir][parity][b*H + j]
__device__ unsigned g_bar[2];              // per-direction barrier counters

__global__ void reset_kernel() {
    int gid = blockIdx.x * blockDim.x + threadIdx.x;
    if (gid < 2 * B_SZ * H_SZ) {
        int dir = gid / (B_SZ * H_SZ);
        g_h[dir][0][gid % (B_SZ * H_SZ)] = 0.0f;
    }
    if (gid < 2) g_bar[gid] = 0u;
}

// dynamic smem layout (floats):
//   sWh  [0,     4096)   Wh[:, j0:j0+16]   row i * 16 + jt
//   sWx  [4096,  8192)   Wx[:, j0:j0+16]
//   sRed [8192,  9216)   float4[256] k-partials
//   sH   [9216, 11520)   h transposed, pitch 9: sH[i*9 + b]
//   sX   [11520,13824)   x_t transposed, pitch 9
//   sB   [13824,13840)   bias slice
#define SMEM_FLOATS 13840
#define SMEM_BYTES  (SMEM_FLOATS * 4)

__global__ __launch_bounds__(256, 1) void rnn_kernel(
    const float* __restrict__ x,
    const float* __restrict__ Wx_f, const float* __restrict__ Wh_f, const float* __restrict__ b_f,
    const float* __restrict__ Wx_b, const float* __restrict__ Wh_b, const float* __restrict__ b_b,
    float* __restrict__ out)
{
    extern __shared__ float sm[];
    float* sWh  = sm;
    float* sWx  = sm + 4096;
    float* sRed = sm + 8192;
    float* sH   = sm + 9216;
    float* sX   = sm + 11520;
    float* sB   = sm + 13824;

    const int t   = threadIdx.x;
    const int dir = blockIdx.x >> 6;        // 0 = fwd, 1 = bwd
    const int blk = blockIdx.x & 63;
    const int j0  = (blk & 15) << 4;        // 16 j-slices of 16 cols
    const int b0  = (blk >> 4) << 3;        // 4 b-slices of 8 rows

    const float* Wx   = dir ? Wx_b : Wx_f;
    const float* Wh   = dir ? Wh_b : Wh_f;
    const float* bias = dir ? b_b  : b_f;

    // preload weight slices into smem (once)
    for (int idx = t; idx < 4096; idx += 256) {
        int i = idx >> 4, jt = idx & 15;
        sWh[idx] = Wh[i * H_SZ + j0 + jt];
        sWx[idx] = Wx[i * H_SZ + j0 + jt];
    }
    if (t < 16) sB[t] = bias[j0 + t];
    __syncthreads();

    // compute-thread coordinates: 4 j-quad x 8 batch x 8 k-chunks
    const int jq  = t & 3;           // j-quad (4 cols via float4)
    const int bb  = (t >> 2) & 7;    // batch row within slice
    const int kk  = t >> 5;          // k-chunk (warp id)
    const int ib  = kk << 5;         // 32 i's per chunk

    for (int s = 0; s < S_SZ; ++s) {
        const int sx = dir ? (S_SZ - 1 - s) : s;

        // stage h (L2, coherent via ldcg) and x_t into smem, transposed [i][b] pitch 9
        const float* hsrc = g_h[dir][s & 1];
        #pragma unroll
        for (int r = 0; r < 2; ++r) {
            int q  = t + (r << 8);        // 0..511 quads
            int b  = q >> 6;              // 0..7
            int iq = (q & 63) << 2;       // 0..252
            float4 hv = __ldcg((const float4*)(hsrc + (b0 + b) * H_SZ + iq));
            sH[(iq + 0) * 9 + b] = hv.x;
            sH[(iq + 1) * 9 + b] = hv.y;
            sH[(iq + 2) * 9 + b] = hv.z;
            sH[(iq + 3) * 9 + b] = hv.w;
            float4 xv = *(const float4*)(x + ((size_t)(b0 + b) * S_SZ + sx) * D_SZ + iq);
            sX[(iq + 0) * 9 + b] = xv.x;
            sX[(iq + 1) * 9 + b] = xv.y;
            sX[(iq + 2) * 9 + b] = xv.z;
            sX[(iq + 3) * 9 + b] = xv.w;
        }
        __syncthreads();

        // partial dot products: acc[j] = sum_{i in chunk} h[b][i]*Wh[i][j] + x[b][i]*Wx[i][j]
        float4 acc = make_float4(0.f, 0.f, 0.f, 0.f);
        #pragma unroll
        for (int ii = 0; ii < 32; ++ii) {
            int i = ib + ii;
            float  hv = sH[i * 9 + bb];
            float4 w  = *(const float4*)(sWh + (i << 4) + (jq << 2));
            acc.x = fmaf(hv, w.x, acc.x);
            acc.y = fmaf(hv, w.y, acc.y);
            acc.z = fmaf(hv, w.z, acc.z);
            acc.w = fmaf(hv, w.w, acc.w);
        }
        #pragma unroll
        for (int ii = 0; ii < 32; ++ii) {
            int i = ib + ii;
            float  xv = sX[i * 9 + bb];
            float4 w  = *(const float4*)(sWx + (i << 4) + (jq << 2));
            acc.x = fmaf(xv, w.x, acc.x);
            acc.y = fmaf(xv, w.y, acc.y);
            acc.z = fmaf(xv, w.z, acc.z);
            acc.w = fmaf(xv, w.w, acc.w);
        }
        ((float4*)sRed)[t] = acc;
        __syncthreads();

        // reduce 8 k-partials, add bias, tanh, write h_next + output
        if (t < 128) {
            int jt = t & 15;
            int b  = t >> 4;
            float sum = sB[jt];
            #pragma unroll
            for (int k = 0; k < 8; ++k)
                sum += sRed[jt + (b << 4) + (k << 7)];
            float hnew = tanhf(sum);
            __stcg(&g_h[dir][(s + 1) & 1][(b0 + b) * H_SZ + j0 + jt], hnew);
            out[((size_t)(b0 + b) * S_SZ + sx) * (2 * H_SZ) + dir * H_SZ + j0 + jt] = hnew;
        }

        // per-direction grid barrier (skip after last step)
        if (s + 1 < S_SZ) {
            __threadfence();
            __syncthreads();
            if (t == 0) {
                unsigned target = (unsigned)NBLK_DIR * (unsigned)(s + 1);
                atomicAdd(&g_bar[dir], 1u);
                while (atomicAdd(&g_bar[dir], 0u) < target)
                    __nanosleep(32);
                __threadfence();
            }
            __syncthreads();
        }
    }
}

extern "C" void kernel_launch(void* const* d_in, const int* in_sizes, int n_in,
                              void* d_out, int out_size)
{
    const float* x    = (const float*)d_in[0];
    const float* Wx_f = (const float*)d_in[1];
    const float* Wh_f = (const float*)d_in[2];
    const float* b_f  = (const float*)d_in[3];
    const float* Wx_b = (const float*)d_in[4];
    const float* Wh_b = (const float*)d_in[5];
    const float* b_b  = (const float*)d_in[6];
    float* out = (float*)d_out;

    cudaFuncSetAttribute(rnn_kernel, cudaFuncAttributeMaxDynamicSharedMemorySize, SMEM_BYTES);

    reset_kernel<<<16, 1024>>>();
    rnn_kernel<<<2 * NBLK_DIR, 256, SMEM_BYTES>>>(x, Wx_f, Wh_f, b_f, Wx_b, Wh_b, b_b, out);
}

// round 4
// speedup vs baseline: 4.6224x; 4.5286x over previous
#include <cuda_runtime.h>
#include <cstdint>

// Bidirectional tanh-Elman RNN, B=32, S=2048, D=H=256, fp32.
//
// Phase 1 (xp_kernel): xp[dir] = x @ Wx_dir + b_dir  -> 128MB device scratch.
// Phase 2 (rnn_kernel): 64 clusters of 2 CTAs; cluster = one (dir, batch).
//   Each CTA holds half of Wh (its 128 output columns) in REGISTERS
//   (128 regs/thread), h vector lives in smem, halves exchanged each step
//   via DSMEM st.async + mbarrier. No device-wide barrier, no L2 ping-pong.

#define S_SZ 2048
#define H_SZ 256
#define B_SZ 32

__device__ float g_xp[2u * 65536u * 256u];   // [dir][b*S + s][j]  128 MB scratch

// ---------------------------------------------------------------------------
// Phase 1: input projection GEMM (fp32), rows = flattened (b, s)
// ---------------------------------------------------------------------------
#define XP_ROWS 64
#define XP_KC   64
#define XP_SMEM_FLOATS (XP_KC * 256 + XP_KC * 64)   // sW + sXT = 20480 floats

__global__ __launch_bounds__(256, 2) void xp_kernel(
    const float* __restrict__ x,
    const float* __restrict__ Wx_f, const float* __restrict__ b_f,
    const float* __restrict__ Wx_b, const float* __restrict__ b_b)
{
    extern __shared__ float sm[];
    float* sW  = sm;                 // [64][256]  sW[ii*256 + j]
    float* sXT = sm + XP_KC * 256;   // [64][64]   sXT[ii*64 + r]

    const int dir  = blockIdx.y;
    const int row0 = blockIdx.x * XP_ROWS;
    const float* W    = dir ? Wx_b : Wx_f;
    const float* bias = dir ? b_b  : b_f;
    const int t = threadIdx.x;
    const int j = t;                 // output column

    float acc[XP_ROWS];
    const float bv = bias[j];
    #pragma unroll
    for (int r = 0; r < XP_ROWS; ++r) acc[r] = bv;

    for (int i0 = 0; i0 < H_SZ; i0 += XP_KC) {
        // stage W chunk [64 i][256 j] (coalesced)
        for (int idx = t; idx < XP_KC * 256; idx += 256)
            sW[idx] = W[(i0 + (idx >> 8)) * H_SZ + (idx & 255)];
        // stage x chunk transposed: thread t handles row r = t>>2, i-range (t&3)*16
        {
            int r  = t >> 2;
            int iq = (t & 3) * 16;
            const float* xr = x + (size_t)(row0 + r) * H_SZ + i0 + iq;
            #pragma unroll
            for (int k = 0; k < 4; ++k) {
                float4 v = *(const float4*)(xr + k * 4);
                sXT[(iq + k*4 + 0) * 64 + r] = v.x;
                sXT[(iq + k*4 + 1) * 64 + r] = v.y;
                sXT[(iq + k*4 + 2) * 64 + r] = v.z;
                sXT[(iq + k*4 + 3) * 64 + r] = v.w;
            }
        }
        __syncthreads();
        for (int ii = 0; ii < XP_KC; ++ii) {
            float wv = sW[ii * 256 + j];
            const float4* xv = (const float4*)(sXT + ii * 64);
            #pragma unroll
            for (int r4 = 0; r4 < 16; ++r4) {
                float4 v = xv[r4];           // broadcast
                acc[r4*4+0] = fmaf(v.x, wv, acc[r4*4+0]);
                acc[r4*4+1] = fmaf(v.y, wv, acc[r4*4+1]);
                acc[r4*4+2] = fmaf(v.z, wv, acc[r4*4+2]);
                acc[r4*4+3] = fmaf(v.w, wv, acc[r4*4+3]);
            }
        }
        __syncthreads();
    }
    float* dst = g_xp + ((size_t)dir * 65536u + row0) * 256 + j;
    #pragma unroll
    for (int r = 0; r < XP_ROWS; ++r) dst[(size_t)r * 256] = acc[r];
}

// ---------------------------------------------------------------------------
// Phase 2: recurrence. grid = 128 CTAs (clusters of 2), 256 threads.
// cluster c = dir*32 + b; rank = j-half. thread: kh = t>>7 (k-half), jl = t&127.
// ---------------------------------------------------------------------------
__device__ __forceinline__ uint32_t smem_u32(const void* p) {
    uint32_t a;
    asm("{ .reg .u64 tmp; cvta.to.shared.u64 tmp, %1; cvt.u32.u64 %0, tmp; }"
        : "=r"(a) : "l"(p));
    return a;
}

__global__ __launch_bounds__(256, 1) __cluster_dims__(2, 1, 1)
void rnn_kernel(const float* __restrict__ Wh_f,
                const float* __restrict__ Wh_b,
                float* __restrict__ out)
{
    __shared__ float sH[2][H_SZ];          // full h vector, double-buffered
    __shared__ float sRed[128];            // k-partials from kh=1
    __shared__ __align__(8) unsigned long long sBar;

    const int t     = threadIdx.x;
    const int rank  = blockIdx.x & 1;      // j-half owned by this CTA
    const int c     = blockIdx.x >> 1;
    const int dir   = c >> 5;
    const int b     = c & 31;
    const int kh    = t >> 7;
    const int jl    = t & 127;
    const int jglob = rank * 128 + jl;

    const float* Wh = dir ? Wh_b : Wh_f;

    // Wh[:, jglob] in registers: w[ii] = Wh[kh*128+ii][jglob]
    float w[128];
    #pragma unroll
    for (int ii = 0; ii < 128; ++ii)
        w[ii] = Wh[(kh * 128 + ii) * H_SZ + jglob];

    // init h = 0, init mbarrier (1 arrival/generation: our own expect_tx)
    sH[0][t] = 0.0f;
    const uint32_t barLocal = smem_u32(&sBar);
    const uint32_t shBase   = smem_u32(&sH[0][0]);
    if (t == 0)
        asm volatile("mbarrier.init.shared.b64 [%0], %1;" :: "r"(barLocal), "r"(1) : "memory");
    __syncthreads();
    asm volatile("barrier.cluster.arrive.aligned;" ::: "memory");
    asm volatile("barrier.cluster.wait.aligned;"   ::: "memory");

    uint32_t peerBar, peerSh;
    {
        uint32_t pr = rank ^ 1;
        asm("mapa.shared::cluster.u32 %0, %1, %2;" : "=r"(peerBar) : "r"(barLocal), "r"(pr));
        asm("mapa.shared::cluster.u32 %0, %1, %2;" : "=r"(peerSh)  : "r"(shBase),   "r"(pr));
    }

    const float* xp_base  = g_xp + ((size_t)dir * 65536u + (size_t)b * S_SZ) * 256 + jglob;
    float*       out_base = out + (size_t)b * S_SZ * 512 + dir * 256 + jglob;

    int sx = dir ? (S_SZ - 1) : 0;
    const int sstep = dir ? -1 : 1;
    float xpv = (t < 128) ? __ldg(xp_base + (size_t)sx * 256) : 0.0f;

    for (int s = 0; s < S_SZ; ++s) {
        // declare expected incoming bytes for this generation (peer's 128 floats)
        if (t == 0 && s + 1 < S_SZ)
            asm volatile("mbarrier.arrive.expect_tx.shared.b64 _, [%0], %1;"
                         :: "r"(barLocal), "r"(512) : "memory");

        // prefetch next step's xp
        float xpn = 0.0f;
        if (t < 128 && s + 1 < S_SZ)
            xpn = __ldg(xp_base + (size_t)(sx + sstep) * 256);

        // partial GEMV over this thread's k-half (weights in registers,
        // h broadcast from smem)
        const float* hb = sH[s & 1] + (kh << 7);
        float a0 = 0.f, a1 = 0.f, a2 = 0.f, a3 = 0.f;
        #pragma unroll
        for (int q = 0; q < 32; ++q) {
            float4 hv = *(const float4*)(hb + (q << 2));   // broadcast LDS.128
            a0 = fmaf(hv.x, w[4*q+0], a0);
            a1 = fmaf(hv.y, w[4*q+1], a1);
            a2 = fmaf(hv.z, w[4*q+2], a2);
            a3 = fmaf(hv.w, w[4*q+3], a3);
        }
        float acc = (a0 + a1) + (a2 + a3);

        if (kh) sRed[jl] = acc;
        __syncthreads();

        if (t < 128) {
            float hnew = tanhf(acc + sRed[jl] + xpv);
            int nb = (s + 1) & 1;
            sH[nb][jglob] = hnew;                           // local copy
            out_base[(size_t)sx * 512] = hnew;              // output (coalesced)
            if (s + 1 < S_SZ) {
                // remote copy into peer's h buffer; tx credited to peer's bar
                uint32_t dst = peerSh + (uint32_t)(nb * 256 + jglob) * 4u;
                asm volatile(
                    "st.async.shared::cluster.mbarrier::complete_tx::bytes.u32 [%0], %1, [%2];"
                    :: "r"(dst), "r"(__float_as_uint(hnew)), "r"(peerBar) : "memory");
            }
        }
        xpv = xpn;
        __syncthreads();   // local sH[nb] writes visible; sRed safe for reuse

        if (s + 1 < S_SZ) {
            // wait for peer's half of h_next (parity = s & 1)
            uint32_t parity = (uint32_t)(s & 1);
            asm volatile(
                "{\n\t.reg .pred P;\n\t"
                "WL_%=:\n\t"
                "mbarrier.try_wait.parity.acquire.cluster.shared::cta.b64 P, [%0], %1, 0x989680;\n\t"
                "@!P bra WL_%=;\n\t}"
                :: "r"(barLocal), "r"(parity) : "memory");
        }
        sx += sstep;
    }
}

// ---------------------------------------------------------------------------
extern "C" void kernel_launch(void* const* d_in, const int* in_sizes, int n_in,
                              void* d_out, int out_size)
{
    const float* x    = (const float*)d_in[0];
    const float* Wx_f = (const float*)d_in[1];
    const float* Wh_f = (const float*)d_in[2];
    const float* b_f  = (const float*)d_in[3];
    const float* Wx_b = (const float*)d_in[4];
    const float* Wh_b = (const float*)d_in[5];
    const float* b_b  = (const float*)d_in[6];
    float* out = (float*)d_out;

    cudaFuncSetAttribute(xp_kernel, cudaFuncAttributeMaxDynamicSharedMemorySize,
                         XP_SMEM_FLOATS * 4);

    dim3 xpgrid(65536 / XP_ROWS, 2);
    xp_kernel<<<xpgrid, 256, XP_SMEM_FLOATS * 4>>>(x, Wx_f, b_f, Wx_b, b_b);
    rnn_kernel<<<128, 256>>>(Wh_f, Wh_b, out);
}

// round 5
// speedup vs baseline: 4.6272x; 1.0010x over previous
#include <cuda_runtime.h>
#include <cstdint>

// Bidirectional tanh-Elman RNN, B=32, S=2048, D=H=256, fp32.
//
// Phase 1 (xp_kernel): xp[dir] = x @ Wx_dir + b_dir  -> 128MB device scratch.
// Phase 2 (rnn_kernel): 64 clusters of 2 CTAs; cluster = one (dir, batch).
//   Each CTA holds half of Wh (its 128 output columns) in REGISTERS
//   (128 regs/thread), h vector lives in smem, halves exchanged each step
//   via DSMEM st.async + mbarrier. No device-wide barrier, no L2 ping-pong.

#define S_SZ 2048
#define H_SZ 256
#define B_SZ 32

__device__ float g_xp[2u * 65536u * 256u];   // [dir][b*S + s][j]  128 MB scratch

// ---------------------------------------------------------------------------
// Phase 1: input projection GEMM (fp32), rows = flattened (b, s)
// ---------------------------------------------------------------------------
#define XP_ROWS 64
#define XP_KC   64
#define XP_SMEM_FLOATS (XP_KC * 256 + XP_KC * 64)   // sW + sXT = 20480 floats

__global__ __launch_bounds__(256, 2) void xp_kernel(
    const float* __restrict__ x,
    const float* __restrict__ Wx_f, const float* __restrict__ b_f,
    const float* __restrict__ Wx_b, const float* __restrict__ b_b)
{
    extern __shared__ float sm[];
    float* sW  = sm;                 // [64][256]  sW[ii*256 + j]
    float* sXT = sm + XP_KC * 256;   // [64][64]   sXT[ii*64 + r]

    const int dir  = blockIdx.y;
    const int row0 = blockIdx.x * XP_ROWS;
    const float* W    = dir ? Wx_b : Wx_f;
    const float* bias = dir ? b_b  : b_f;
    const int t = threadIdx.x;
    const int j = t;                 // output column

    float acc[XP_ROWS];
    const float bv = bias[j];
    #pragma unroll
    for (int r = 0; r < XP_ROWS; ++r) acc[r] = bv;

    for (int i0 = 0; i0 < H_SZ; i0 += XP_KC) {
        // stage W chunk [64 i][256 j] (coalesced)
        for (int idx = t; idx < XP_KC * 256; idx += 256)
            sW[idx] = W[(i0 + (idx >> 8)) * H_SZ + (idx & 255)];
        // stage x chunk transposed: thread t handles row r = t>>2, i-range (t&3)*16
        {
            int r  = t >> 2;
            int iq = (t & 3) * 16;
            const float* xr = x + (size_t)(row0 + r) * H_SZ + i0 + iq;
            #pragma unroll
            for (int k = 0; k < 4; ++k) {
                float4 v = *(const float4*)(xr + k * 4);
                sXT[(iq + k*4 + 0) * 64 + r] = v.x;
                sXT[(iq + k*4 + 1) * 64 + r] = v.y;
                sXT[(iq + k*4 + 2) * 64 + r] = v.z;
                sXT[(iq + k*4 + 3) * 64 + r] = v.w;
            }
        }
        __syncthreads();
        for (int ii = 0; ii < XP_KC; ++ii) {
            float wv = sW[ii * 256 + j];
            const float4* xv = (const float4*)(sXT + ii * 64);
            #pragma unroll
            for (int r4 = 0; r4 < 16; ++r4) {
                float4 v = xv[r4];           // broadcast
                acc[r4*4+0] = fmaf(v.x, wv, acc[r4*4+0]);
                acc[r4*4+1] = fmaf(v.y, wv, acc[r4*4+1]);
                acc[r4*4+2] = fmaf(v.z, wv, acc[r4*4+2]);
                acc[r4*4+3] = fmaf(v.w, wv, acc[r4*4+3]);
            }
        }
        __syncthreads();
    }
    float* dst = g_xp + ((size_t)dir * 65536u + row0) * 256 + j;
    #pragma unroll
    for (int r = 0; r < XP_ROWS; ++r) dst[(size_t)r * 256] = acc[r];
}

// ---------------------------------------------------------------------------
// Phase 2: recurrence. grid = 128 CTAs (clusters of 2), 256 threads.
// cluster c = dir*32 + b; rank = j-half. thread: kh = t>>7 (k-half), jl = t&127.
// ---------------------------------------------------------------------------
__device__ __forceinline__ uint32_t smem_u32(const void* p) {
    uint32_t a;
    asm("{ .reg .u64 tmp; cvta.to.shared.u64 tmp, %1; cvt.u32.u64 %0, tmp; }"
        : "=r"(a) : "l"(p));
    return a;
}

__global__ __launch_bounds__(256, 1) __cluster_dims__(2, 1, 1)
void rnn_kernel(const float* __restrict__ Wh_f,
                const float* __restrict__ Wh_b,
                float* __restrict__ out)
{
    __shared__ float sH[2][H_SZ];          // full h vector, double-buffered
    __shared__ float sRed[128];            // k-partials from kh=1
    __shared__ __align__(8) unsigned long long sBar;

    const int t     = threadIdx.x;
    const int rank  = blockIdx.x & 1;      // j-half owned by this CTA
    const int c     = blockIdx.x >> 1;
    const int dir   = c >> 5;
    const int b     = c & 31;
    const int kh    = t >> 7;
    const int jl    = t & 127;
    const int jglob = rank * 128 + jl;

    const float* Wh = dir ? Wh_b : Wh_f;

    // Wh[:, jglob] in registers: w[ii] = Wh[kh*128+ii][jglob]
    float w[128];
    #pragma unroll
    for (int ii = 0; ii < 128; ++ii)
        w[ii] = Wh[(kh * 128 + ii) * H_SZ + jglob];

    // init h = 0, init mbarrier (1 arrival/generation: our own expect_tx)
    sH[0][t] = 0.0f;
    const uint32_t barLocal = smem_u32(&sBar);
    const uint32_t shBase   = smem_u32(&sH[0][0]);
    if (t == 0)
        asm volatile("mbarrier.init.shared.b64 [%0], %1;" :: "r"(barLocal), "r"(1) : "memory");
    __syncthreads();
    asm volatile("barrier.cluster.arrive.aligned;" ::: "memory");
    asm volatile("barrier.cluster.wait.aligned;"   ::: "memory");

    uint32_t peerBar, peerSh;
    {
        uint32_t pr = rank ^ 1;
        asm("mapa.shared::cluster.u32 %0, %1, %2;" : "=r"(peerBar) : "r"(barLocal), "r"(pr));
        asm("mapa.shared::cluster.u32 %0, %1, %2;" : "=r"(peerSh)  : "r"(shBase),   "r"(pr));
    }

    const float* xp_base  = g_xp + ((size_t)dir * 65536u + (size_t)b * S_SZ) * 256 + jglob;
    float*       out_base = out + (size_t)b * S_SZ * 512 + dir * 256 + jglob;

    int sx = dir ? (S_SZ - 1) : 0;
    const int sstep = dir ? -1 : 1;
    float xpv = (t < 128) ? __ldg(xp_base + (size_t)sx * 256) : 0.0f;

    for (int s = 0; s < S_SZ; ++s) {
        // declare expected incoming bytes for this generation (peer's 128 floats)
        if (t == 0 && s + 1 < S_SZ)
            asm volatile("mbarrier.arrive.expect_tx.shared.b64 _, [%0], %1;"
                         :: "r"(barLocal), "r"(512) : "memory");

        // prefetch next step's xp
        float xpn = 0.0f;
        if (t < 128 && s + 1 < S_SZ)
            xpn = __ldg(xp_base + (size_t)(sx + sstep) * 256);

        // partial GEMV over this thread's k-half (weights in registers,
        // h broadcast from smem)
        const float* hb = sH[s & 1] + (kh << 7);
        float a0 = 0.f, a1 = 0.f, a2 = 0.f, a3 = 0.f;
        #pragma unroll
        for (int q = 0; q < 32; ++q) {
            float4 hv = *(const float4*)(hb + (q << 2));   // broadcast LDS.128
            a0 = fmaf(hv.x, w[4*q+0], a0);
            a1 = fmaf(hv.y, w[4*q+1], a1);
            a2 = fmaf(hv.z, w[4*q+2], a2);
            a3 = fmaf(hv.w, w[4*q+3], a3);
        }
        float acc = (a0 + a1) + (a2 + a3);

        if (kh) sRed[jl] = acc;
        __syncthreads();

        if (t < 128) {
            float hnew = tanhf(acc + sRed[jl] + xpv);
            int nb = (s + 1) & 1;
            sH[nb][jglob] = hnew;                           // local copy
            out_base[(size_t)sx * 512] = hnew;              // output (coalesced)
            if (s + 1 < S_SZ) {
                // remote copy into peer's h buffer; tx credited to peer's bar
                uint32_t dst = peerSh + (uint32_t)(nb * 256 + jglob) * 4u;
                asm volatile(
                    "st.async.shared::cluster.mbarrier::complete_tx::bytes.u32 [%0], %1, [%2];"
                    :: "r"(dst), "r"(__float_as_uint(hnew)), "r"(peerBar) : "memory");
            }
        }
        xpv = xpn;
        __syncthreads();   // local sH[nb] writes visible; sRed safe for reuse

        if (s + 1 < S_SZ) {
            // wait for peer's half of h_next (parity = s & 1)
            uint32_t parity = (uint32_t)(s & 1);
            asm volatile(
                "{\n\t.reg .pred P;\n\t"
                "WL_%=:\n\t"
                "mbarrier.try_wait.parity.acquire.cluster.shared::cta.b64 P, [%0], %1, 0x989680;\n\t"
                "@!P bra WL_%=;\n\t}"
                :: "r"(barLocal), "r"(parity) : "memory");
        }
        sx += sstep;
    }
}

// ---------------------------------------------------------------------------
extern "C" void kernel_launch(void* const* d_in, const int* in_sizes, int n_in,
                              void* d_out, int out_size)
{
    const float* x    = (const float*)d_in[0];
    const float* Wx_f = (const float*)d_in[1];
    const float* Wh_f = (const float*)d_in[2];
    const float* b_f  = (const float*)d_in[3];
    const float* Wx_b = (const float*)d_in[4];
    const float* Wh_b = (const float*)d_in[5];
    const float* b_b  = (const float*)d_in[6];
    float* out = (float*)d_out;

    cudaFuncSetAttribute(xp_kernel, cudaFuncAttributeMaxDynamicSharedMemorySize,
                         XP_SMEM_FLOATS * 4);

    dim3 xpgrid(65536 / XP_ROWS, 2);
    xp_kernel<<<xpgrid, 256, XP_SMEM_FLOATS * 4>>>(x, Wx_f, b_f, Wx_b, b_b);
    rnn_kernel<<<128, 256>>>(Wh_f, Wh_b, out);
}